// round 9
// baseline (speedup 1.0000x reference)
#include <cuda_runtime.h>
#include <cuda_fp16.h>

#define NC 16
#define EPSV 1e-6f
#define B_DIM 2
#define D_DIM 8
#define H_DIM 96
#define W_DIM 96
#define DHW (D_DIM*H_DIM*W_DIM)     // 73728
#define HW  (H_DIM*W_DIM)           // 9216

// CTA tile: full depth x 4 y x 8 x
#define TD 8
#define TH 4
#define TW 8
#define NTHREADS (TD*TH*TW)         // 256
#define HALO_D (TD+2)               // 10
#define HALO_H (TH+2)               // 6
#define HALO_W (TW+2)               // 10
#define NLOC   (HALO_D*HALO_H*HALO_W) // 600 halo locations
#define PLANE_LOC (HALO_H*HALO_W)   // 60 locations per d-plane
#define LOC_BYTES 48                // 32B fp16 data + 16B pad (48 mod 32 == 16 -> conflict-free LDS.128)
#define SH_BYTES (NLOC*LOC_BYTES)   // 28800 B
#define SV_BYTES (27*NTHREADS*4)    // 27648 B
#define ST_OFF   (SH_BYTES + SV_BYTES)
#define SMEM_BYTES (ST_OFF + 1024)  // 57,472 B -> 3 CTAs/SM

typedef unsigned long long ull;

// ---- packed f32x2 helpers (Blackwell FFMA2 path, PTX-only) ----
__device__ __forceinline__ ull f2fma(ull a, ull b, ull c) {
    ull d; asm("fma.rn.f32x2 %0,%1,%2,%3;" : "=l"(d) : "l"(a), "l"(b), "l"(c)); return d;
}
__device__ __forceinline__ ull f2add(ull a, ull b) {
    ull d; asm("add.rn.f32x2 %0,%1,%2;" : "=l"(d) : "l"(a), "l"(b)); return d;
}
__device__ __forceinline__ ull f2mul(ull a, ull b) {
    ull d; asm("mul.rn.f32x2 %0,%1,%2;" : "=l"(d) : "l"(a), "l"(b)); return d;
}
__device__ __forceinline__ ull pack2(float lo, float hi) {
    ull d; asm("mov.b64 %0,{%1,%2};" : "=l"(d) : "f"(lo), "f"(hi)); return d;
}
__device__ __forceinline__ float2 unpack2(ull a) {
    float2 r; asm("mov.b64 {%0,%1},%2;" : "=f"(r.x), "=f"(r.y) : "l"(a)); return r;
}
__device__ __forceinline__ unsigned h2u(__half2 h) {
    return *reinterpret_cast<unsigned*>(&h);
}
// half2 bits -> packed f32x2 holding X * 2^-112 (bit placement, no F2F).
// X >= 0 (post-relu) so sign handling is unnecessary. hi keeps <=2^-10
// relative mantissa garbage from lo's upper bits (tolerated).
__device__ __forceinline__ ull h2f2s(unsigned u) {
    unsigned lo = (u << 13) & 0x0FFFE000u;
    unsigned hi =  u >> 3;
    return pack2(__uint_as_float(lo), __uint_as_float(hi));
}

#define SCALE_UP   0x1p112f
#define SCALE_DN   0x1p-112f

// 4.7 MB scratch for head output (fp16), channel-contiguous: h[b][d][y][x][c]
__device__ __half g_h[(size_t)B_DIM * DHW * NC];

// ---------------------------------------------------------------------------
// Kernel 1: h = relu(head_w @ x) -> fp16, c-contiguous (2x STG.128 / location).
// ---------------------------------------------------------------------------
__global__ void head_kernel(const float* __restrict__ x,
                            const float* __restrict__ head_w) {
    __shared__ float sw[NC * NC];
    if (threadIdx.x < NC * NC) sw[threadIdx.x] = head_w[threadIdx.x];
    __syncthreads();

    int idx = blockIdx.x * blockDim.x + threadIdx.x;   // over b*D*H*W
    if (idx >= B_DIM * DHW) return;
    int b = idx / DHW;
    int s = idx - b * DHW;

    const float* xb = x + (size_t)b * NC * DHW + s;
    float xv[NC];
#pragma unroll
    for (int c = 0; c < NC; c++) xv[c] = xb[(size_t)c * DHW];

    float hv[NC];
#pragma unroll
    for (int o = 0; o < NC; o++) {
        float a = 0.f;
#pragma unroll
        for (int c = 0; c < NC; c++) a = fmaf(sw[o * NC + c], xv[c], a);
        hv[o] = fmaxf(a, 0.f);
    }
    unsigned hp[8];
#pragma unroll
    for (int j = 0; j < 8; j++)
        hp[j] = h2u(__floats2half2_rn(hv[2*j], hv[2*j+1]));
    uint4* hb = (uint4*)(g_h + (size_t)idx * NC);
    hb[0] = make_uint4(hp[0], hp[1], hp[2], hp[3]);
    hb[1] = make_uint4(hp[4], hp[5], hp[6], hp[7]);
}

// ---------------------------------------------------------------------------
// Kernel 2: per-location rank-degenerate NMF + tail. X cached as fp16 in smem
// (48B-stride, conflict-free LDS.128), bit-converted on load (ALU pipe) with
// the 2^112 scale folded into u; packed f32x2 math.
// ---------------------------------------------------------------------------
__global__ void __launch_bounds__(NTHREADS, 3)
nmf_kernel(const float* __restrict__ tail_w, float* __restrict__ out) {
    extern __shared__ __align__(16) unsigned char smembuf[];
    char*  shb = (char*)smembuf;                    // [p][yy][xx] * 48B fp16 tile
    float* sv  = (float*)(smembuf + SH_BYTES);      // [27][256] per-thread v (f32)
    float* st  = (float*)(smembuf + ST_OFF);        // [256] tail weights

    const int tid = threadIdx.x;
    const int b  = blockIdx.z;
    const int y0 = blockIdx.y * TH;
    const int x0 = blockIdx.x * TW;

    if (tid < NC * NC) st[tid] = tail_w[tid];

    // ---- stage halo tile: 32B/location fp16, coalesced ----
    {
        const size_t hbase = (size_t)b * DHW * NC;
        for (int i = tid; i < NLOC; i += NTHREADS) {
            int xx = i % HALO_W;
            int r  = i / HALO_W;
            int yy = r % HALO_H;
            int p  = r / HALO_H;                       // d-plane 0..9
            int gd = min(max(p - 1, 0), D_DIM - 1);
            int gy = min(max(y0 + yy - 1, 0), H_DIM - 1);
            int gx = min(max(x0 + xx - 1, 0), W_DIM - 1);
            const uint4* src = (const uint4*)(g_h + hbase
                               + (size_t)((gd * H_DIM + gy) * W_DIM + gx) * NC);
            uint4* dst = (uint4*)(shb + i * LOC_BYTES);
            dst[0] = src[0]; dst[1] = src[1];
        }
    }
    __syncthreads();

    const int tx = tid & 7;
    const int ty = (tid >> 3) & 3;
    const int td = tid >> 5;
    const char* shp = shb + ((td * HALO_H + ty) * HALO_W + tx) * LOC_BYTES;

    ull up[8];
#pragma unroll
    for (int j = 0; j < 8; j++) up[j] = 0ull;   // two packed 0.0f

    // ---- init pass: u[c] = mean_k X, v[k] = mean_c X (accumulated at 2^-112) ----
#pragma unroll 1
    for (int kk = 0; kk < 9; kk++) {            // kk = ki*3+kj
        const int ki = kk / 3, kj = kk - 3 * ki;
        const char* pbase = shp + (ki * HALO_W + kj) * LOC_BYTES;
        const int svb = kk * 3 * NTHREADS + tid;
#pragma unroll
        for (int kt = 0; kt < 3; kt++) {
            const uint4* p = (const uint4*)(pbase + kt * (PLANE_LOC * LOC_BYTES));
            uint4 q0 = p[0], q1 = p[1];
            ull xp[8] = {h2f2s(q0.x), h2f2s(q0.y), h2f2s(q0.z), h2f2s(q0.w),
                         h2f2s(q1.x), h2f2s(q1.y), h2f2s(q1.z), h2f2s(q1.w)};
#pragma unroll
            for (int j = 0; j < 8; j++) up[j] = f2add(up[j], xp[j]);
            ull t0 = f2add(xp[0], xp[1]);
            ull t1 = f2add(xp[2], xp[3]);
            ull t2 = f2add(xp[4], xp[5]);
            ull t3 = f2add(xp[6], xp[7]);
            t0 = f2add(t0, t1); t2 = f2add(t2, t3);
            float2 s2 = unpack2(f2add(t0, t2));
            sv[svb + kt * NTHREADS] = (s2.x + s2.y) * (SCALE_UP / 16.f);
        }
    }
    {   // rescale to true u
        const ull c27 = pack2(SCALE_UP / 27.f, SCALE_UP / 27.f);
#pragma unroll
        for (int j = 0; j < 8; j++) up[j] = f2mul(up[j], c27);
    }

    // ---- 3 NMF steps ----
#pragma unroll 1
    for (int step = 0; step < 3; step++) {
        ull uup = 0ull;
#pragma unroll
        for (int j = 0; j < 8; j++) uup = f2fma(up[j], up[j], uup);
        float2 uu2 = unpack2(uup);
        const float t_uu = 3.f * (uu2.x + uu2.y);

        // scale u in place: num = (u*2^112) . (X*2^-112) comes out true-scale
        {
            const ull s112 = pack2(SCALE_UP, SCALE_UP);
#pragma unroll
            for (int j = 0; j < 8; j++) up[j] = f2mul(up[j], s112);
        }

        ull nup[8];
#pragma unroll
        for (int j = 0; j < 8; j++) nup[j] = 0ull;
        float vv = 0.f;

#pragma unroll 1
        for (int kk = 0; kk < 9; kk++) {
            const int ki = kk / 3, kj = kk - 3 * ki;
            const char* pbase = shp + (ki * HALO_W + kj) * LOC_BYTES;
            const int svb = kk * 3 * NTHREADS + tid;
#pragma unroll
            for (int kt = 0; kt < 3; kt++) {
                const uint4* p = (const uint4*)(pbase + kt * (PLANE_LOC * LOC_BYTES));
                uint4 q0 = p[0], q1 = p[1];
                ull xp[8] = {h2f2s(q0.x), h2f2s(q0.y), h2f2s(q0.z), h2f2s(q0.w),
                             h2f2s(q1.x), h2f2s(q1.y), h2f2s(q1.z), h2f2s(q1.w)};

                // num = u . X[:,k]  (2 packed chains, true scale)
                ull np0 = f2mul(up[0], xp[0]);
                np0 = f2fma(up[2], xp[2], np0);
                np0 = f2fma(up[4], xp[4], np0);
                np0 = f2fma(up[6], xp[6], np0);
                ull np1 = f2mul(up[1], xp[1]);
                np1 = f2fma(up[3], xp[3], np1);
                np1 = f2fma(up[5], xp[5], np1);
                np1 = f2fma(up[7], xp[7], np1);
                float2 ns = unpack2(f2add(np0, np1));
                float num = ns.x + ns.y;

                const int svi = svb + kt * NTHREADS;
                float vk = sv[svi];
                float vn = vk * num * __frcp_rn(fmaf(t_uu, vk, EPSV));
                sv[svi] = vn;
                vv = fmaf(vn, vn, vv);
                ull vn2 = pack2(vn, vn);
#pragma unroll
                for (int j = 0; j < 8; j++) nup[j] = f2fma(xp[j], vn2, nup[j]);
            }
        }
        // u' = a*nu~ / (3*vv*2^-112*a + eps); a = u*2^112, nu~ = nu*2^-112
        const float t_vv2 = 3.f * vv * SCALE_DN;
#pragma unroll
        for (int j = 0; j < 8; j++) {
            float2 a  = unpack2(up[j]);
            float2 nb = unpack2(nup[j]);
            float c0 = a.x * nb.x * __frcp_rn(fmaf(t_vv2, a.x, EPSV));
            float c1 = a.y * nb.y * __frcp_rn(fmaf(t_vv2, a.y, EPSV));
            up[j] = pack2(c0, c1);   // back to true scale
        }
    }

    // ---- center tap + tail GEMV + relu (packed) ----
    const float v13 = sv[13 * NTHREADS + tid];
    const ull v13p = pack2(3.f * v13, 3.f * v13);
    ull uvcp[8];
#pragma unroll
    for (int j = 0; j < 8; j++) uvcp[j] = f2mul(up[j], v13p);

    const size_t outbase = (size_t)b * NC * DHW + (size_t)td * HW
                         + (size_t)(y0 + ty) * W_DIM + (x0 + tx);
#pragma unroll
    for (int i = 0; i < NC; i++) {
        const ulonglong2* wr = (const ulonglong2*)(st + i * NC);
        ulonglong2 w0 = wr[0], w1 = wr[1], w2 = wr[2], w3 = wr[3];
        ull acc0 = f2mul(w0.x, uvcp[0]);
        acc0 = f2fma(w1.x, uvcp[2], acc0);
        acc0 = f2fma(w2.x, uvcp[4], acc0);
        acc0 = f2fma(w3.x, uvcp[6], acc0);
        ull acc1 = f2mul(w0.y, uvcp[1]);
        acc1 = f2fma(w1.y, uvcp[3], acc1);
        acc1 = f2fma(w2.y, uvcp[5], acc1);
        acc1 = f2fma(w3.y, uvcp[7], acc1);
        float2 r2 = unpack2(f2add(acc0, acc1));
        out[outbase + (size_t)i * DHW] = fmaxf(r2.x + r2.y, 0.f);
    }
}

// ---------------------------------------------------------------------------
extern "C" void kernel_launch(void* const* d_in, const int* in_sizes, int n_in,
                              void* d_out, int out_size) {
    const float* x      = (const float*)d_in[0];
    const float* head_w = (const float*)d_in[1];
    const float* tail_w = (const float*)d_in[2];
    float* out = (float*)d_out;

    (void)in_sizes; (void)n_in; (void)out_size;

    cudaFuncSetAttribute(nmf_kernel,
                         cudaFuncAttributeMaxDynamicSharedMemorySize,
                         SMEM_BYTES);
    cudaFuncSetAttribute(nmf_kernel,
                         cudaFuncAttributePreferredSharedMemoryCarveout,
                         100);

    {   // head: one thread per spatial location
        int total = B_DIM * DHW;
        int threads = 256;
        int blocks = (total + threads - 1) / threads;
        head_kernel<<<blocks, threads>>>(x, head_w);
    }
    {
        dim3 grid(W_DIM / TW, H_DIM / TH, B_DIM);   // (12, 24, 2) = 576 CTAs
        nmf_kernel<<<grid, NTHREADS, SMEM_BYTES>>>(tail_w, out);
    }
}

// round 11
// speedup vs baseline: 1.0720x; 1.0720x over previous
#include <cuda_runtime.h>

#define NC 16
#define EPSV 1e-6f
#define B_DIM 2
#define D_DIM 8
#define H_DIM 96
#define W_DIM 96
#define DHW (D_DIM*H_DIM*W_DIM)     // 73728
#define HW  (H_DIM*W_DIM)           // 9216

// CTA tile: full depth x 4 y x 8 x
#define TD 8
#define TH 4
#define TW 8
#define NTHREADS (TD*TH*TW)         // 256
#define HALO_D (TD+2)               // 10
#define HALO_H (TH+2)               // 6
#define HALO_W (TW+2)               // 10
#define NLOC   (HALO_D*HALO_H*HALO_W) // 600 halo locations
#define CSTRIDE 20                  // 16 ch + 4 pad floats (conflict-free LDS.128)
#define PLANE  (HALO_H*HALO_W*CSTRIDE)
#define SH_ELEMS (NLOC*CSTRIDE)     // 12000 floats = 48000 B
#define SV_ELEMS (27*NTHREADS)      // 6912 floats  = 27648 B
#define SW_OFF   (SH_ELEMS + SV_ELEMS)
#define SMEM_FLOATS (SW_OFF + 256)  // shared head/tail weight buffer
#define SMEM_BYTES (SMEM_FLOATS * 4)   // 76,672 B -> 3 CTAs/SM (with 1KB/CTA reserve)

typedef unsigned long long ull;

// ---- packed f32x2 helpers (Blackwell FFMA2 path, PTX-only) ----
__device__ __forceinline__ ull f2fma(ull a, ull b, ull c) {
    ull d; asm("fma.rn.f32x2 %0,%1,%2,%3;" : "=l"(d) : "l"(a), "l"(b), "l"(c)); return d;
}
__device__ __forceinline__ ull f2add(ull a, ull b) {
    ull d; asm("add.rn.f32x2 %0,%1,%2;" : "=l"(d) : "l"(a), "l"(b)); return d;
}
__device__ __forceinline__ ull f2mul(ull a, ull b) {
    ull d; asm("mul.rn.f32x2 %0,%1,%2;" : "=l"(d) : "l"(a), "l"(b)); return d;
}
__device__ __forceinline__ ull pack2(float lo, float hi) {
    ull d; asm("mov.b64 %0,{%1,%2};" : "=l"(d) : "f"(lo), "f"(hi)); return d;
}
__device__ __forceinline__ float2 unpack2(ull a) {
    float2 r; asm("mov.b64 {%0,%1},%2;" : "=f"(r.x), "=f"(r.y) : "l"(a)); return r;
}

// ---------------------------------------------------------------------------
// Single fused kernel: in-tile head GEMV -> smem, rank-degenerate NMF, tail.
// ---------------------------------------------------------------------------
__global__ void __launch_bounds__(NTHREADS, 3)
nmf_kernel(const float* __restrict__ x,
           const float* __restrict__ head_w,
           const float* __restrict__ tail_w,
           float* __restrict__ out) {
    extern __shared__ float smem[];
    float* sh = smem;                 // [p][yy][xx][CSTRIDE] h halo tile (fp32)
    float* sv = smem + SH_ELEMS;      // [27][256] per-thread v
    float* sw = smem + SW_OFF;        // [256] head weights, then tail weights

    const int tid = threadIdx.x;
    const int b  = blockIdx.z;
    const int y0 = blockIdx.y * TH;
    const int x0 = blockIdx.x * TW;

    // ---- phase 0: head weights into shared buffer ----
    if (tid < NC * NC) sw[tid] = head_w[tid];
    __syncthreads();

    // ---- staging: fused head GEMV for the 600-location halo tile ----
    {
        const size_t xbase = (size_t)b * NC * DHW;
        for (int i = tid; i < NLOC; i += NTHREADS) {
            int xx = i % HALO_W;
            int r  = i / HALO_W;
            int yy = r % HALO_H;
            int p  = r / HALO_H;                       // d-plane 0..9
            int gd = min(max(p - 1, 0), D_DIM - 1);
            int gy = min(max(y0 + yy - 1, 0), H_DIM - 1);
            int gx = min(max(x0 + xx - 1, 0), W_DIM - 1);
            const float* xp = x + xbase + (size_t)(gd * HW + gy * W_DIM + gx);

            float xv[NC];
#pragma unroll
            for (int c = 0; c < NC; c++) xv[c] = xp[(size_t)c * DHW];

            float4* dst = (float4*)(sh + i * CSTRIDE);
#pragma unroll
            for (int q = 0; q < 4; q++) {
                float h0 = 0.f, h1 = 0.f, h2 = 0.f, h3 = 0.f;
#pragma unroll
                for (int c = 0; c < NC; c++) {
                    h0 = fmaf(sw[(4*q+0) * NC + c], xv[c], h0);
                    h1 = fmaf(sw[(4*q+1) * NC + c], xv[c], h1);
                    h2 = fmaf(sw[(4*q+2) * NC + c], xv[c], h2);
                    h3 = fmaf(sw[(4*q+3) * NC + c], xv[c], h3);
                }
                dst[q] = make_float4(fmaxf(h0, 0.f), fmaxf(h1, 0.f),
                                     fmaxf(h2, 0.f), fmaxf(h3, 0.f));
            }
        }
    }
    __syncthreads();

    // swap weight buffer to tail weights
    if (tid < NC * NC) sw[tid] = tail_w[tid];
    __syncthreads();

    const int tx = tid & 7;
    const int ty = (tid >> 3) & 3;
    const int td = tid >> 5;
    const float* shp = sh + ((td * HALO_H + ty) * HALO_W + tx) * CSTRIDE;

    ull up[8];
#pragma unroll
    for (int j = 0; j < 8; j++) up[j] = 0ull;   // two packed 0.0f

    // ---- init pass: u[c] = mean_k X, v[k] = mean_c X ----
#pragma unroll 1
    for (int kk = 0; kk < 9; kk++) {            // kk = ki*3+kj
        const int ki = kk / 3, kj = kk - 3 * ki;
        const float* pbase = shp + (ki * HALO_W + kj) * CSTRIDE;
        const int svb = kk * 3 * NTHREADS + tid;
#pragma unroll
        for (int kt = 0; kt < 3; kt++) {
            const ulonglong2* p = (const ulonglong2*)(pbase + kt * PLANE);
            ulonglong2 q0 = p[0], q1 = p[1];
            ull xp[8] = {q0.x, q0.y, q1.x, q1.y, 0, 0, 0, 0};
            {
                const ulonglong2* p2 = p + 2;
                ulonglong2 q2 = p2[0], q3 = p2[1];
                xp[4] = q2.x; xp[5] = q2.y; xp[6] = q3.x; xp[7] = q3.y;
            }
#pragma unroll
            for (int j = 0; j < 8; j++) up[j] = f2add(up[j], xp[j]);
            ull t0 = f2add(xp[0], xp[1]);
            ull t1 = f2add(xp[2], xp[3]);
            ull t2 = f2add(xp[4], xp[5]);
            ull t3 = f2add(xp[6], xp[7]);
            t0 = f2add(t0, t1); t2 = f2add(t2, t3);
            float2 s2 = unpack2(f2add(t0, t2));
            sv[svb + kt * NTHREADS] = (s2.x + s2.y) * (1.f / 16.f);
        }
    }
    {
        const ull c27 = pack2(1.f / 27.f, 1.f / 27.f);
#pragma unroll
        for (int j = 0; j < 8; j++) up[j] = f2mul(up[j], c27);
    }

    // ---- 3 NMF steps ----
#pragma unroll 1
    for (int step = 0; step < 3; step++) {
        ull uup = 0ull;
#pragma unroll
        for (int j = 0; j < 8; j++) uup = f2fma(up[j], up[j], uup);
        float2 uu2 = unpack2(uup);
        const float t_uu = 3.f * (uu2.x + uu2.y);
        const bool keep_all = (step < 2);

        ull nup[8];
#pragma unroll
        for (int j = 0; j < 8; j++) nup[j] = 0ull;
        float vv = 0.f;

#pragma unroll 1
        for (int kk = 0; kk < 9; kk++) {
            const int ki = kk / 3, kj = kk - 3 * ki;
            const float* pbase = shp + (ki * HALO_W + kj) * CSTRIDE;
            const int svb = kk * 3 * NTHREADS + tid;
#pragma unroll
            for (int kt = 0; kt < 3; kt++) {
                const ulonglong2* p = (const ulonglong2*)(pbase + kt * PLANE);
                ulonglong2 q0 = p[0], q1 = p[1], q2 = p[2], q3 = p[3];
                ull xp[8] = {q0.x, q0.y, q1.x, q1.y, q2.x, q2.y, q3.x, q3.y};

                // num = u . X[:,k]  (2 packed chains)
                ull np0 = f2mul(up[0], xp[0]);
                np0 = f2fma(up[2], xp[2], np0);
                np0 = f2fma(up[4], xp[4], np0);
                np0 = f2fma(up[6], xp[6], np0);
                ull np1 = f2mul(up[1], xp[1]);
                np1 = f2fma(up[3], xp[3], np1);
                np1 = f2fma(up[5], xp[5], np1);
                np1 = f2fma(up[7], xp[7], np1);
                float2 ns = unpack2(f2add(np0, np1));
                float num = ns.x + ns.y;

                const int svi = svb + kt * NTHREADS;
                float vk = sv[svi];
                float vn = vk * num * __frcp_rn(fmaf(t_uu, vk, EPSV));
                // last step: only v[13] (kk==4, kt==1) is ever read again
                if (keep_all || (kt == 1 && kk == 4)) sv[svi] = vn;
                vv = fmaf(vn, vn, vv);
                ull vn2 = pack2(vn, vn);
#pragma unroll
                for (int j = 0; j < 8; j++) nup[j] = f2fma(xp[j], vn2, nup[j]);
            }
        }
        const float t_vv = 3.f * vv;
#pragma unroll
        for (int j = 0; j < 8; j++) {
            float2 a  = unpack2(up[j]);
            float2 nb = unpack2(nup[j]);
            float c0 = a.x * nb.x * __frcp_rn(fmaf(t_vv, a.x, EPSV));
            float c1 = a.y * nb.y * __frcp_rn(fmaf(t_vv, a.y, EPSV));
            up[j] = pack2(c0, c1);
        }
    }

    // ---- center tap + tail GEMV + relu (packed) ----
    const float v13 = sv[13 * NTHREADS + tid];
    const ull v13p = pack2(3.f * v13, 3.f * v13);
    ull uvcp[8];
#pragma unroll
    for (int j = 0; j < 8; j++) uvcp[j] = f2mul(up[j], v13p);

    const size_t outbase = (size_t)b * NC * DHW + (size_t)td * HW
                         + (size_t)(y0 + ty) * W_DIM + (x0 + tx);
#pragma unroll
    for (int i = 0; i < NC; i++) {
        const ulonglong2* wr = (const ulonglong2*)(sw + i * NC);
        ulonglong2 w0 = wr[0], w1 = wr[1], w2 = wr[2], w3 = wr[3];
        ull acc0 = f2mul(w0.x, uvcp[0]);
        acc0 = f2fma(w1.x, uvcp[2], acc0);
        acc0 = f2fma(w2.x, uvcp[4], acc0);
        acc0 = f2fma(w3.x, uvcp[6], acc0);
        ull acc1 = f2mul(w0.y, uvcp[1]);
        acc1 = f2fma(w1.y, uvcp[3], acc1);
        acc1 = f2fma(w2.y, uvcp[5], acc1);
        acc1 = f2fma(w3.y, uvcp[7], acc1);
        float2 r2 = unpack2(f2add(acc0, acc1));
        out[outbase + (size_t)i * DHW] = fmaxf(r2.x + r2.y, 0.f);
    }
}

// ---------------------------------------------------------------------------
extern "C" void kernel_launch(void* const* d_in, const int* in_sizes, int n_in,
                              void* d_out, int out_size) {
    const float* x      = (const float*)d_in[0];
    const float* head_w = (const float*)d_in[1];
    const float* tail_w = (const float*)d_in[2];
    float* out = (float*)d_out;

    (void)in_sizes; (void)n_in; (void)out_size;

    cudaFuncSetAttribute(nmf_kernel,
                         cudaFuncAttributeMaxDynamicSharedMemorySize,
                         SMEM_BYTES);
    cudaFuncSetAttribute(nmf_kernel,
                         cudaFuncAttributePreferredSharedMemoryCarveout,
                         100);

    dim3 grid(W_DIM / TW, H_DIM / TH, B_DIM);   // (12, 24, 2) = 576 CTAs
    nmf_kernel<<<grid, NTHREADS, SMEM_BYTES>>>(x, head_w, tail_w, out);
}